// round 12
// baseline (speedup 1.0000x reference)
#include <cuda_runtime.h>
#include <cuda_bf16.h>
#include <cstdint>

// Problem constants
#define BB 32
#define HH 480
#define WW 864
#define HW (HH * WW)
#define KHALF 7
#define CHUNK 24
#define ROWS (CHUNK + 2 * KHALF)    // 38 halo rows
#define NCH (HH / CHUNK)            // 20
#define NBLK (NCH * BB)             // 640 blocks
#define TPB 224                     // 7 warps
#define ACT 216                     // 216 * 4 = 864 cols in gather
#define NWRD 27                     // 864/32 mask words per row
#define SWB 112                     // byte-plane row stride (28 words, 4 pad bytes)
#define VS 29                       // vA/vB row stride in words (idx0 = left pad)

__device__ double   g_psum[NBLK];
__device__ int      g_pcnt[NBLK];
__device__ unsigned g_ticket = 0;

// 15-tap horizontal OR-dilation of a 32-col bit word with its neighbors.
__device__ __forceinline__ unsigned dil15(unsigned L, unsigned C, unsigned R) {
    unsigned long long x = ((unsigned long long)C << 32) | (unsigned long long)L;
    x |= x << 1; x |= x << 2; x |= x << 4;          // bit m = OR of bits m-7..m
    unsigned long long y = ((unsigned long long)R << 32) | (unsigned long long)C;
    y |= y >> 1; y |= y >> 2; y |= y >> 4;          // bit m = OR of bits m..m+7
    return (unsigned)(x >> 32) | (unsigned)y;
}

__global__ __launch_bounds__(TPB, 6) void bl_fused(const float* __restrict__ logits,
                                                   const int*   __restrict__ labels,
                                                   float* __restrict__ out) {
    // Bit planes (1 bit/px, byte-addressed): A = np==0, B = np==255, I = ignore.
    __shared__ unsigned char sA[ROWS * SWB];
    __shared__ unsigned char sB[ROWS * SWB];
    __shared__ unsigned char sI[ROWS * SWB];
    __shared__ unsigned vA[CHUNK * VS];      // vertical 15-OR of A
    __shared__ unsigned vB[CHUNK * VS];      // vertical 15-OR of B
    __shared__ unsigned vM[CHUNK * NWRD];    // final valid mask

    const int chunk = blockIdx.x;
    const int b     = blockIdx.y;
    const int h0    = chunk * CHUNK;
    const int t     = threadIdx.x;
    const int wid   = t >> 5, lane = t & 31;

    // ---- Phase 0: zero planes + vA/vB (halos, pads rely on this) ----
    for (int i = t; i < (ROWS * SWB) / 4; i += TPB) {
        ((unsigned*)sA)[i] = 0u; ((unsigned*)sB)[i] = 0u; ((unsigned*)sI)[i] = 0u;
    }
    for (int i = t; i < CHUNK * VS; i += TPB) { vA[i] = 0u; vB[i] = 0u; }
    __syncthreads();

    // ---- Phase 1: ingest labels -> bit planes (8 px/thread, coalesced) ----
#pragma unroll 4
    for (int u = t; u < ROWS * 108; u += TPB) {
        const int r  = u / 108;
        const int j  = u - r * 108;            // byte index: cols 8j..8j+7
        const int gh = h0 - KHALF + r;
        if ((unsigned)gh < (unsigned)HH) {
            const int4* p = (const int4*)(labels + (size_t)((size_t)b * HH + gh) * WW + (size_t)8 * j);
            const int4 x = p[0];
            const int4 y = p[1];
            // labels in {0,1,255}: isB = (l ^ (l>>7)) & 1 ; isI = (l>>7) & 1
            unsigned bBv = ((unsigned)((x.x ^ (x.x >> 7)) & 1))
                         | ((unsigned)((x.y ^ (x.y >> 7)) & 1) << 1)
                         | ((unsigned)((x.z ^ (x.z >> 7)) & 1) << 2)
                         | ((unsigned)((x.w ^ (x.w >> 7)) & 1) << 3)
                         | ((unsigned)((y.x ^ (y.x >> 7)) & 1) << 4)
                         | ((unsigned)((y.y ^ (y.y >> 7)) & 1) << 5)
                         | ((unsigned)((y.z ^ (y.z >> 7)) & 1) << 6)
                         | ((unsigned)((y.w ^ (y.w >> 7)) & 1) << 7);
            unsigned bIv = ((unsigned)((x.x >> 7) & 1))
                         | ((unsigned)((x.y >> 7) & 1) << 1)
                         | ((unsigned)((x.z >> 7) & 1) << 2)
                         | ((unsigned)((x.w >> 7) & 1) << 3)
                         | ((unsigned)((y.x >> 7) & 1) << 4)
                         | ((unsigned)((y.y >> 7) & 1) << 5)
                         | ((unsigned)((y.z >> 7) & 1) << 6)
                         | ((unsigned)((y.w >> 7) & 1) << 7);
            sB[r * SWB + j] = (unsigned char)bBv;
            sI[r * SWB + j] = (unsigned char)bIv;
            sA[r * SWB + j] = (unsigned char)(bBv ^ 0xFFu);   // A = ~B in-bounds
        }
    }
    __syncthreads();

    // ---- Phase 2: vertical 15-row OR per (output row, word) — 3 tasks/thread ----
#pragma unroll
    for (int q = 0; q < 3; q++) {
        const int u = t + q * TPB;              // CHUNK*28 = 672 = 3*TPB exactly
        const int i = u / 28, w = u - i * 28;   // w = 0..27 (27 = pad word)
        const unsigned char* pa = sA + i * SWB + 4 * w;
        const unsigned char* pb = sB + i * SWB + 4 * w;
        unsigned oa = 0, ob = 0;
#pragma unroll
        for (int k = 0; k < 15; k++) {
            oa |= *(const unsigned*)(pa + k * SWB);
            ob |= *(const unsigned*)(pb + k * SWB);
        }
        vA[i * VS + 1 + w] = oa;
        vB[i * VS + 1 + w] = ob;
    }
    __syncthreads();

    // ---- Phase 3: horizontal dil15 + validity ----
#pragma unroll 3
    for (int u = t; u < CHUNK * NWRD; u += TPB) {
        const int i = u / NWRD, w = u - i * NWRD;
        const unsigned* va = vA + i * VS + 1 + w;
        const unsigned* vb = vB + i * VS + 1 + w;
        const unsigned da = dil15(va[-1], va[0], va[1]);
        const unsigned db = dil15(vb[-1], vb[0], vb[1]);
        const unsigned Ic = *(const unsigned*)(sI + (i + KHALF) * SWB + 4 * w);
        vM[u] = da & db & ~Ic;
    }
    __syncthreads();

    // ---- Phase 4: streaming NLL gather ----
    float lsum = 0.0f;
    int   lcnt = 0;
    if (t < ACT) {
        const int w  = t >> 3;
        const int sh = (t & 7) * 4;
        const float* __restrict__ lg0 = logits + (size_t)b * 2 * HW + (size_t)h0 * WW + 4 * t;
        const float* __restrict__ lg1 = lg0 + HW;

#pragma unroll 8
        for (int i = 0; i < CHUNK; i++) {
            const unsigned nv = (vM[i * NWRD + w] >> sh) & 0xFu;
            const unsigned nc = ((*(const unsigned*)(sB + (i + KHALF) * SWB + 4 * w)) >> sh) & 0xFu;
            const float4 v0 = *(const float4*)(lg0 + i * WW);
            const float4 v1 = *(const float4*)(lg1 + i * WW);
            if (nv & 1u) lsum += (nc & 1u) ? v1.x : v0.x;
            if (nv & 2u) lsum += (nc & 2u) ? v1.y : v0.y;
            if (nv & 4u) lsum += (nc & 4u) ? v1.z : v0.z;
            if (nv & 8u) lsum += (nc & 8u) ? v1.w : v0.w;
            lcnt += __popc(nv);
        }
    }

    // ---- Block + grid reduction (ticketed last-block finalize) ----
#pragma unroll
    for (int o = 16; o > 0; o >>= 1) {
        lsum += __shfl_down_sync(0xFFFFFFFFu, lsum, o);
        lcnt += __shfl_down_sync(0xFFFFFFFFu, lcnt, o);
    }
    __shared__ float ws[TPB / 32];
    __shared__ int   wc[TPB / 32];
    __shared__ bool  s_last;
    if (lane == 0) { ws[wid] = lsum; wc[wid] = lcnt; }
    __syncthreads();

    const int bid = b * NCH + chunk;
    if (t == 0) {
        double bs = 0.0; int bc = 0;
#pragma unroll
        for (int i = 0; i < TPB / 32; i++) { bs += (double)ws[i]; bc += wc[i]; }
        g_psum[bid] = bs;
        g_pcnt[bid] = bc;
        __threadfence();
        const unsigned r = atomicAdd(&g_ticket, 1u);
        s_last = (r == NBLK - 1);
    }
    __syncthreads();

    if (s_last) {
        double ds = 0.0; long long dc = 0;
        for (int i = t; i < NBLK; i += TPB) { ds += g_psum[i]; dc += g_pcnt[i]; }
#pragma unroll
        for (int o = 16; o > 0; o >>= 1) {
            ds += __shfl_down_sync(0xFFFFFFFFu, ds, o);
            dc += __shfl_down_sync(0xFFFFFFFFu, dc, o);
        }
        __shared__ double    fs[TPB / 32];
        __shared__ long long fc[TPB / 32];
        if (lane == 0) { fs[wid] = ds; fc[wid] = dc; }
        __syncthreads();
        if (t == 0) {
            double S = 0.0; long long C = 0;
#pragma unroll
            for (int i = 0; i < TPB / 32; i++) { S += fs[i]; C += fc[i]; }
            if (C < 1) C = 1;
            out[0] = (float)(-S / (double)C);
            g_ticket = 0;                     // reset for next graph replay
        }
    }
}

extern "C" void kernel_launch(void* const* d_in, const int* in_sizes, int n_in,
                              void* d_out, int out_size) {
    const float* logits = (const float*)d_in[0];
    const int*   labels = (const int*)d_in[1];
    float*       out    = (float*)d_out;

    bl_fused<<<dim3(NCH, BB), TPB>>>(logits, labels, out);
}

// round 15
// speedup vs baseline: 1.0065x; 1.0065x over previous
#include <cuda_runtime.h>
#include <cuda_bf16.h>
#include <cstdint>

// Problem constants
#define BB 32
#define HH 480
#define WW 864
#define HW (HH * WW)
#define KHALF 7
#define CHUNK 16
#define ROWS (CHUNK + 2 * KHALF)    // 30 halo rows
#define NCH (HH / CHUNK)            // 30
#define NBLK (NCH * BB)             // 960 blocks -> 6.5/SM, single wave
#define TPB 224                     // 7 warps
#define ACT 216                     // 216 * 4 = 864 cols in gather
#define NWRD 27                     // 864/32 mask words per row
#define SWB 112                     // byte-plane row stride (28 words, 4 pad bytes)
#define VS 29                       // vA/vB row stride in words (idx0 = left pad)

__device__ double   g_psum[NBLK];
__device__ int      g_pcnt[NBLK];
__device__ unsigned g_ticket = 0;

// 15-tap horizontal OR-dilation of a 32-col bit word with its neighbors.
__device__ __forceinline__ unsigned dil15(unsigned L, unsigned C, unsigned R) {
    unsigned long long x = ((unsigned long long)C << 32) | (unsigned long long)L;
    x |= x << 1; x |= x << 2; x |= x << 4;          // bit m = OR of bits m-7..m
    unsigned long long y = ((unsigned long long)R << 32) | (unsigned long long)C;
    y |= y >> 1; y |= y >> 2; y |= y >> 4;          // bit m = OR of bits m..m+7
    return (unsigned)(x >> 32) | (unsigned)y;
}

__global__ __launch_bounds__(TPB, 7) void bl_fused(const float* __restrict__ logits,
                                                   const int*   __restrict__ labels,
                                                   float* __restrict__ out) {
    // Bit planes (1 bit/px, byte-addressed): A = np==0, B = np==255, I = ignore.
    __shared__ unsigned char sA[ROWS * SWB];
    __shared__ unsigned char sB[ROWS * SWB];
    __shared__ unsigned char sI[ROWS * SWB];
    __shared__ unsigned vA[CHUNK * VS];      // vertical 15-OR of A
    __shared__ unsigned vB[CHUNK * VS];      // vertical 15-OR of B
    __shared__ unsigned vM[CHUNK * NWRD];    // final valid mask

    const int chunk = blockIdx.x;
    const int b     = blockIdx.y;
    const int h0    = chunk * CHUNK;
    const int t     = threadIdx.x;
    const int wid   = t >> 5, lane = t & 31;

    // ---- Phase 0: zero planes + vA/vB (halos, pads rely on this) ----
    for (int i = t; i < (ROWS * SWB) / 4; i += TPB) {
        ((unsigned*)sA)[i] = 0u; ((unsigned*)sB)[i] = 0u; ((unsigned*)sI)[i] = 0u;
    }
    for (int i = t; i < CHUNK * VS; i += TPB) { vA[i] = 0u; vB[i] = 0u; }
    __syncthreads();

    // ---- Phase 1: ingest labels -> bit planes (8 px/thread, coalesced) ----
#pragma unroll 4
    for (int u = t; u < ROWS * 108; u += TPB) {
        const int r  = u / 108;
        const int j  = u - r * 108;            // byte index: cols 8j..8j+7
        const int gh = h0 - KHALF + r;
        if ((unsigned)gh < (unsigned)HH) {
            const int4* p = (const int4*)(labels + (size_t)((size_t)b * HH + gh) * WW + (size_t)8 * j);
            const int4 x = p[0];
            const int4 y = p[1];
            // labels in {0,1,255}: isB = (l ^ (l>>7)) & 1 ; isI = (l>>7) & 1
            unsigned bBv = ((unsigned)((x.x ^ (x.x >> 7)) & 1))
                         | ((unsigned)((x.y ^ (x.y >> 7)) & 1) << 1)
                         | ((unsigned)((x.z ^ (x.z >> 7)) & 1) << 2)
                         | ((unsigned)((x.w ^ (x.w >> 7)) & 1) << 3)
                         | ((unsigned)((y.x ^ (y.x >> 7)) & 1) << 4)
                         | ((unsigned)((y.y ^ (y.y >> 7)) & 1) << 5)
                         | ((unsigned)((y.z ^ (y.z >> 7)) & 1) << 6)
                         | ((unsigned)((y.w ^ (y.w >> 7)) & 1) << 7);
            unsigned bIv = ((unsigned)((x.x >> 7) & 1))
                         | ((unsigned)((x.y >> 7) & 1) << 1)
                         | ((unsigned)((x.z >> 7) & 1) << 2)
                         | ((unsigned)((x.w >> 7) & 1) << 3)
                         | ((unsigned)((y.x >> 7) & 1) << 4)
                         | ((unsigned)((y.y >> 7) & 1) << 5)
                         | ((unsigned)((y.z >> 7) & 1) << 6)
                         | ((unsigned)((y.w >> 7) & 1) << 7);
            sB[r * SWB + j] = (unsigned char)bBv;
            sI[r * SWB + j] = (unsigned char)bIv;
            sA[r * SWB + j] = (unsigned char)(bBv ^ 0xFFu);   // A = ~B in-bounds
        }
    }
    __syncthreads();

    // ---- Phase 2: vertical 15-row OR per (output row, word) — 2 tasks/thread ----
#pragma unroll
    for (int q = 0; q < 2; q++) {
        const int u = t + q * TPB;              // CHUNK*28 = 448 = 2*TPB exactly
        const int i = u / 28, w = u - i * 28;   // w = 0..27 (27 = pad word)
        const unsigned char* pa = sA + i * SWB + 4 * w;
        const unsigned char* pb = sB + i * SWB + 4 * w;
        unsigned oa = 0, ob = 0;
#pragma unroll
        for (int k = 0; k < 15; k++) {
            oa |= *(const unsigned*)(pa + k * SWB);
            ob |= *(const unsigned*)(pb + k * SWB);
        }
        vA[i * VS + 1 + w] = oa;
        vB[i * VS + 1 + w] = ob;
    }
    __syncthreads();

    // ---- Phase 3: horizontal dil15 + validity ----
#pragma unroll 2
    for (int u = t; u < CHUNK * NWRD; u += TPB) {
        const int i = u / NWRD, w = u - i * NWRD;
        const unsigned* va = vA + i * VS + 1 + w;
        const unsigned* vb = vB + i * VS + 1 + w;
        const unsigned da = dil15(va[-1], va[0], va[1]);
        const unsigned db = dil15(vb[-1], vb[0], vb[1]);
        const unsigned Ic = *(const unsigned*)(sI + (i + KHALF) * SWB + 4 * w);
        vM[u] = da & db & ~Ic;
    }
    __syncthreads();

    // ---- Phase 4: streaming NLL gather ----
    float lsum = 0.0f;
    int   lcnt = 0;
    if (t < ACT) {
        const int w  = t >> 3;
        const int sh = (t & 7) * 4;
        const float* __restrict__ lg0 = logits + (size_t)b * 2 * HW + (size_t)h0 * WW + 4 * t;
        const float* __restrict__ lg1 = lg0 + HW;

#pragma unroll 8
        for (int i = 0; i < CHUNK; i++) {
            const unsigned nv = (vM[i * NWRD + w] >> sh) & 0xFu;
            const unsigned nc = ((*(const unsigned*)(sB + (i + KHALF) * SWB + 4 * w)) >> sh) & 0xFu;
            const float4 v0 = *(const float4*)(lg0 + i * WW);
            const float4 v1 = *(const float4*)(lg1 + i * WW);
            if (nv & 1u) lsum += (nc & 1u) ? v1.x : v0.x;
            if (nv & 2u) lsum += (nc & 2u) ? v1.y : v0.y;
            if (nv & 4u) lsum += (nc & 4u) ? v1.z : v0.z;
            if (nv & 8u) lsum += (nc & 8u) ? v1.w : v0.w;
            lcnt += __popc(nv);
        }
    }

    // ---- Block + grid reduction (ticketed last-block finalize) ----
#pragma unroll
    for (int o = 16; o > 0; o >>= 1) {
        lsum += __shfl_down_sync(0xFFFFFFFFu, lsum, o);
        lcnt += __shfl_down_sync(0xFFFFFFFFu, lcnt, o);
    }
    __shared__ float ws[TPB / 32];
    __shared__ int   wc[TPB / 32];
    __shared__ bool  s_last;
    if (lane == 0) { ws[wid] = lsum; wc[wid] = lcnt; }
    __syncthreads();

    const int bid = b * NCH + chunk;
    if (t == 0) {
        double bs = 0.0; int bc = 0;
#pragma unroll
        for (int i = 0; i < TPB / 32; i++) { bs += (double)ws[i]; bc += wc[i]; }
        g_psum[bid] = bs;
        g_pcnt[bid] = bc;
        __threadfence();
        const unsigned r = atomicAdd(&g_ticket, 1u);
        s_last = (r == NBLK - 1);
    }
    __syncthreads();

    if (s_last) {
        double ds = 0.0; long long dc = 0;
        for (int i = t; i < NBLK; i += TPB) { ds += g_psum[i]; dc += g_pcnt[i]; }
#pragma unroll
        for (int o = 16; o > 0; o >>= 1) {
            ds += __shfl_down_sync(0xFFFFFFFFu, ds, o);
            dc += __shfl_down_sync(0xFFFFFFFFu, dc, o);
        }
        __shared__ double    fs[TPB / 32];
        __shared__ long long fc[TPB / 32];
        if (lane == 0) { fs[wid] = ds; fc[wid] = dc; }
        __syncthreads();
        if (t == 0) {
            double S = 0.0; long long C = 0;
#pragma unroll
            for (int i = 0; i < TPB / 32; i++) { S += fs[i]; C += fc[i]; }
            if (C < 1) C = 1;
            out[0] = (float)(-S / (double)C);
            g_ticket = 0;                     // reset for next graph replay
        }
    }
}

extern "C" void kernel_launch(void* const* d_in, const int* in_sizes, int n_in,
                              void* d_out, int out_size) {
    const float* logits = (const float*)d_in[0];
    const int*   labels = (const int*)d_in[1];
    float*       out    = (float*)d_out;

    bl_fused<<<dim3(NCH, BB), TPB>>>(logits, labels, out);
}